// round 15
// baseline (speedup 1.0000x reference)
#include <cuda_runtime.h>
#include <cuda_fp16.h>
#include <math.h>
#include <stdint.h>

#define D_MODEL 2048
#define S_LEN   2048
#define BATCH   2
#define NHEADS  16
#define NKV     4
#define NGRP    4
#define HD      128
#define KVD     (NKV*HD)        /* 512  */
#define MROWS   (BATCH*S_LEN)   /* 4096 */
#define NQKV    (D_MODEL + 2*KVD)   /* 3072 */

// -------- scratch (device globals; no allocation allowed) --------
__device__ __half g_Xh  [(size_t)MROWS * D_MODEL];
__device__ __half g_Wqkv[(size_t)NQKV * D_MODEL];
__device__ __half g_Woh [(size_t)D_MODEL * D_MODEL];
__device__ __half g_Qh  [(size_t)MROWS * D_MODEL];
__device__ __half g_Kh  [(size_t)MROWS * KVD];
__device__ __half g_Vh  [(size_t)MROWS * KVD];
__device__ __half g_VtH [(size_t)BATCH * NKV * HD * S_LEN];
__device__ __half g_ctxH[(size_t)MROWS * D_MODEL];
__device__ float  g_inv [(size_t)BATCH * NHEADS * S_LEN];

// ---------------- helpers ----------------
__device__ __forceinline__ uint32_t smem_u32(const void* p) {
    uint32_t a;
    asm("{ .reg .u64 t; cvta.to.shared.u64 t, %1; cvt.u32.u64 %0, t; }"
        : "=r"(a) : "l"(p));
    return a;
}
__device__ __forceinline__ void ldsm4(uint32_t* r, uint32_t addr) {
    asm volatile("ldmatrix.sync.aligned.m8n8.x4.shared.b16 {%0,%1,%2,%3}, [%4];"
        : "=r"(r[0]), "=r"(r[1]), "=r"(r[2]), "=r"(r[3]) : "r"(addr));
}
__device__ __forceinline__ void mma16816(float* d, const uint32_t* a, const uint32_t* b) {
    asm volatile(
        "mma.sync.aligned.m16n8k16.row.col.f32.f16.f16.f32 "
        "{%0,%1,%2,%3}, {%4,%5,%6,%7}, {%8,%9}, {%0,%1,%2,%3};"
        : "+f"(d[0]), "+f"(d[1]), "+f"(d[2]), "+f"(d[3])
        : "r"(a[0]), "r"(a[1]), "r"(a[2]), "r"(a[3]), "r"(b[0]), "r"(b[1]));
}
__device__ __forceinline__ void sts16(uint32_t addr, uint4 u) {
    asm volatile("st.shared.v4.b32 [%0], {%1,%2,%3,%4};"
        :: "r"(addr), "r"(u.x), "r"(u.y), "r"(u.z), "r"(u.w) : "memory");
}
__device__ __forceinline__ void cpa16(uint32_t dst, const void* src) {
    asm volatile("cp.async.cg.shared.global [%0], [%1], 16;"
        :: "r"(dst), "l"(src) : "memory");
}
#define CP_COMMIT() asm volatile("cp.async.commit_group;" ::: "memory")
#define CP_WAIT(n)  asm volatile("cp.async.wait_group %0;" :: "n"(n) : "memory")
__device__ __forceinline__ uint32_t pack_h2(float a, float b) {
    __half2 h = __floats2half2_rn(a, b);
    return *(uint32_t*)&h;
}

// ============================================================================
// Fused fp32 -> fp16 conversion for query + all weights (one launch)
// ============================================================================
#define N4_X  (MROWS * D_MODEL / 4)     /* 2097152 */
#define N4_WQ (D_MODEL * D_MODEL / 4)   /* 1048576 */
#define N4_WK (KVD * D_MODEL / 4)       /* 262144  */
#define N4_ALL (N4_X + N4_WQ + 2*N4_WK + N4_WQ)

__global__ void cvt_all_kernel(
    const float* __restrict__ X,  const float* __restrict__ Wq,
    const float* __restrict__ Wk, const float* __restrict__ Wv,
    const float* __restrict__ Wo,
    __half* __restrict__ Xh, __half* __restrict__ Wqkv, __half* __restrict__ Woh)
{
    int i = blockIdx.x * blockDim.x + threadIdx.x;
    if (i >= N4_ALL) return;
    const float* src; __half* dst; int off;
    if (i < N4_X) {
        src = X; dst = Xh; off = 0;
    } else if (i < N4_X + N4_WQ) {
        src = Wq; dst = Wqkv; off = N4_X;
    } else if (i < N4_X + N4_WQ + N4_WK) {
        src = Wk; dst = Wqkv + (size_t)D_MODEL * D_MODEL; off = N4_X + N4_WQ;
    } else if (i < N4_X + N4_WQ + 2 * N4_WK) {
        src = Wv; dst = Wqkv + (size_t)(D_MODEL + KVD) * D_MODEL; off = N4_X + N4_WQ + N4_WK;
    } else {
        src = Wo; dst = Woh; off = N4_X + N4_WQ + 2 * N4_WK;
    }
    const int j = i - off;
    float4 v = ((const float4*)src)[j];
    __half2 h0 = __floats2half2_rn(v.x, v.y);
    __half2 h1 = __floats2half2_rn(v.z, v.w);
    uint2 u; u.x = *(uint32_t*)&h0; u.y = *(uint32_t*)&h1;
    ((uint2*)dst)[j] = u;
}

// ============================================================================
// All-half GEMM core, 3-stage cp.async pipeline (R12, proven).
// ============================================================================
#define ROWB   80
#define AB_SZ  (128 * ROWB)
#define BB_SZ  (256 * ROWB)
#define STAGE  (AB_SZ + BB_SZ)

__device__ __forceinline__ void gemm_core(
    const __half* __restrict__ A, int lda,
    const __half* __restrict__ B, int ldb,
    int Kd, int m0, int n0, uint32_t sb, float (&acc)[4][8][4])
{
    const int tid  = threadIdx.x;
    const int lane = tid & 31;
    const int wid  = tid >> 5;
    const int wm   = wid & 1;
    const int wn   = wid >> 1;

#pragma unroll
    for (int i = 0; i < 4; i++)
#pragma unroll
        for (int j = 0; j < 8; j++)
#pragma unroll
            for (int r = 0; r < 4; r++) acc[i][j][r] = 0.0f;

    const uint32_t aoff = (uint32_t)((wm * 64 + ((lane >> 3) & 1) * 8 + (lane & 7)) * ROWB
                                     + (lane >> 4) * 16);
    const uint32_t boff = (uint32_t)((wn * 64 + (lane & 7)) * ROWB + (lane >> 3) * 16);

    const int nc = Kd >> 5;

    auto issue = [&](int c) {
        const uint32_t st = sb + (uint32_t)(c % 3) * STAGE;
        const int kc = c * 32;
#pragma unroll
        for (int i = 0; i < 2; i++) {
            const int idx = tid + i * 256;
            const int row = idx >> 2, k8 = idx & 3;
            cpa16(st + (uint32_t)(row * ROWB + k8 * 16),
                  A + (size_t)(m0 + row) * lda + kc + k8 * 8);
        }
#pragma unroll
        for (int i = 0; i < 4; i++) {
            const int idx = tid + i * 256;
            const int row = idx >> 2, k8 = idx & 3;
            cpa16(st + AB_SZ + (uint32_t)(row * ROWB + k8 * 16),
                  B + (size_t)(n0 + row) * ldb + kc + k8 * 8);
        }
        CP_COMMIT();
    };

    issue(0);
    if (nc > 1) issue(1);

    for (int c = 0; c < nc; c++) {
        if (c + 2 < nc)      { issue(c + 2); CP_WAIT(2); }
        else if (c + 1 < nc) { CP_WAIT(1); }
        else                 { CP_WAIT(0); }
        __syncthreads();

        const uint32_t sA = sb + (uint32_t)(c % 3) * STAGE;
        const uint32_t sB = sA + AB_SZ;
        uint32_t bfr[8][4];
#pragma unroll
        for (int tn = 0; tn < 8; tn++)
            ldsm4(bfr[tn], sB + boff + tn * 8 * ROWB);
#pragma unroll
        for (int tm = 0; tm < 4; tm++) {
            uint32_t a0[4], a1[4];
            ldsm4(a0, sA + aoff + tm * 16 * ROWB);
            ldsm4(a1, sA + aoff + tm * 16 * ROWB + 32);
#pragma unroll
            for (int tn = 0; tn < 8; tn++) {
                mma16816(acc[tm][tn], a0, &bfr[tn][0]);
                mma16816(acc[tm][tn], a1, &bfr[tn][2]);
            }
        }
        __syncthreads();
    }
}

// ============================================================================
// QKV projection
// ============================================================================
__global__ __launch_bounds__(256, 1) void qkv_kernel(
    const __half* __restrict__ X, const __half* __restrict__ Wqkv,
    const float* __restrict__ bq, const float* __restrict__ bk, const float* __restrict__ bv,
    __half* __restrict__ Qo, __half* __restrict__ Ko, __half* __restrict__ Vo,
    float qscale)
{
    extern __shared__ __align__(16) char dsm[];
    const int m0 = blockIdx.y * 128;
    const int n0 = blockIdx.x * 256;

    float acc[4][8][4];
    gemm_core(X, D_MODEL, Wqkv, D_MODEL, D_MODEL, m0, n0, smem_u32(dsm), acc);

    __half* C; const float* bias; int ldc, nbase; float scale;
    if (n0 < D_MODEL)            { C = Qo; bias = bq; ldc = D_MODEL; nbase = 0;              scale = qscale; }
    else if (n0 < D_MODEL + KVD) { C = Ko; bias = bk; ldc = KVD;     nbase = D_MODEL;        scale = 1.0f; }
    else                         { C = Vo; bias = bv; ldc = KVD;     nbase = D_MODEL + KVD;  scale = 1.0f; }

    const int lane = threadIdx.x & 31;
    const int wid  = threadIdx.x >> 5;
    const int wm   = wid & 1;
    const int wn   = wid >> 1;
    const int rm   = m0 + wm * 64 + (lane >> 2);
#pragma unroll
    for (int tm = 0; tm < 4; tm++) {
        const int r = rm + tm * 16;
#pragma unroll
        for (int tn = 0; tn < 8; tn++) {
            const int c = n0 - nbase + wn * 64 + tn * 8 + (lane & 3) * 2;
            const float b0 = bias[c];
            const float b1 = bias[c + 1];
            *(__half2*)(C + (size_t)r       * ldc + c) =
                __floats2half2_rn((acc[tm][tn][0] + b0) * scale, (acc[tm][tn][1] + b1) * scale);
            *(__half2*)(C + (size_t)(r + 8) * ldc + c) =
                __floats2half2_rn((acc[tm][tn][2] + b0) * scale, (acc[tm][tn][3] + b1) * scale);
        }
    }
}

// ============================================================================
// RoPE
// ============================================================================
__global__ void rope_kernel(__half* __restrict__ K, const __half* __restrict__ V,
                            __half* __restrict__ Vt)
{
    const int total = MROWS * KVD / 2;
    int idx = blockIdx.x * blockDim.x + threadIdx.x;
    if (idx >= 2 * total) return;
    const bool isK = (idx < total);
    int i = isK ? idx : idx - total;

    const int pair = i & 63;
    const int rest = i >> 6;
    const int kvi  = rest & (NKV - 1);
    const int row  = rest / NKV;
    const int s    = row & (S_LEN - 1);
    const int b    = row >> 11;

    const float inv_freq = powf(10000.0f, -(float)(2 * pair) / (float)HD);
    const float ang = (float)s * inv_freq;
    const float c = cosf(ang), sn = sinf(ang);

    const size_t base = (size_t)row * KVD + kvi * HD;
    if (isK) {
        float x1 = __half2float(K[base + pair]);
        float x2 = __half2float(K[base + pair + 64]);
        K[base + pair]      = __float2half_rn(x1 * c - x2 * sn);
        K[base + pair + 64] = __float2half_rn(x2 * c + x1 * sn);
    } else {
        float x1 = __half2float(V[base + pair]);
        float x2 = __half2float(V[base + pair + 64]);
        __half* vt = Vt + (size_t)(b * NKV + kvi) * HD * S_LEN;
        vt[(size_t)pair * S_LEN + s]        = __float2half_rn(x1 * c - x2 * sn);
        vt[(size_t)(pair + 64) * S_LEN + s] = __float2half_rn(x2 * c + x1 * sn);
    }
}

// ============================================================================
// Flash forward (pass 1): scores + exp + AV -> ctx; per-row inv saved.
// ============================================================================
#define FROWB 272
#define FTILE (128 * FROWB)

__global__ __launch_bounds__(256) void flash_fwd(
    const __half* __restrict__ Q, const __half* __restrict__ K,
    const __half* __restrict__ Vt, __half* __restrict__ ctx,
    float* __restrict__ invOut)
{
    const int qb = gridDim.x - 1 - blockIdx.x;
    const int z  = blockIdx.y;
    const int b  = z / NHEADS;
    const int h  = z % NHEADS;
    const int kv = h / NGRP;
    const int m0 = qb * 128;

    extern __shared__ __align__(16) char dsm[];
    const uint32_t sQ  = smem_u32(dsm);
    const uint32_t sK0 = sQ + FTILE;
    const uint32_t sV0 = sQ + 3 * FTILE;

    const int tid  = threadIdx.x;
    const int lane = tid & 31;
    const int w    = tid >> 5;

    const int frow = tid & 127;
    const int fhb  = (tid >> 7) * 64;

    {
        const __half* src = Q + (size_t)(b * S_LEN + m0 + frow) * D_MODEL + h * HD + fhb;
        const uint32_t dst = sQ + (uint32_t)(frow * FROWB + fhb * 2);
#pragma unroll
        for (int j = 0; j < 8; j++)
            sts16(dst + j * 16, *(const uint4*)(src + j * 8));
    }
    __syncthreads();

    uint32_t qa[8][4];
    {
        const uint32_t aoff = sQ + (uint32_t)((w * 16 + ((lane >> 3) & 1) * 8 + (lane & 7)) * FROWB
                                              + (lane >> 4) * 16);
#pragma unroll
        for (int kc = 0; kc < 8; kc++) ldsm4(qa[kc], aoff + kc * 32);
    }

    const int r0 = m0 + w * 16 + (lane >> 2);
    const int r1 = r0 + 8;

    float O[16][4];
#pragma unroll
    for (int dt = 0; dt < 16; dt++)
#pragma unroll
        for (int r = 0; r < 4; r++) O[dt][r] = 0.0f;
    float rs0 = 0.0f, rs1 = 0.0f;

    const uint32_t bbase = (uint32_t)((lane & 7) * FROWB + (lane >> 3) * 16);
    const uint32_t fdst  = (uint32_t)(frow * FROWB + fhb * 2);

    auto issue_kv = [&](int kt) {
        const uint32_t stK = sK0 + (uint32_t)(kt & 1) * FTILE;
        const uint32_t stV = sV0 + (uint32_t)(kt & 1) * FTILE;
        const __half* ksrc = K + (size_t)(b * S_LEN + kt * 128 + frow) * KVD + kv * HD + fhb;
        const __half* vsrc = Vt + (size_t)((b * NKV + kv) * HD + frow) * S_LEN + kt * 128 + fhb;
#pragma unroll
        for (int j = 0; j < 8; j++) {
            cpa16(stK + fdst + j * 16, ksrc + j * 8);
            cpa16(stV + fdst + j * 16, vsrc + j * 8);
        }
        CP_COMMIT();
    };

    issue_kv(0);
    for (int kt = 0; kt <= qb; kt++) {
        if (kt < qb) { issue_kv(kt + 1); CP_WAIT(1); }
        else         { CP_WAIT(0); }
        __syncthreads();

        const uint32_t sKs = sK0 + (uint32_t)(kt & 1) * FTILE;
        const uint32_t sVs = sV0 + (uint32_t)(kt & 1) * FTILE;

        float Sa[16][4];
#pragma unroll
        for (int j = 0; j < 16; j++)
#pragma unroll
            for (int r = 0; r < 4; r++) Sa[j][r] = 0.0f;
#pragma unroll
        for (int g = 0; g < 4; g++) {
#pragma unroll
            for (int j = 0; j < 16; j++) {
                uint32_t kb[4];
                ldsm4(kb, sKs + bbase + (uint32_t)(j * 8 * FROWB + g * 64));
                mma16816(Sa[j], qa[2 * g],     &kb[0]);
                mma16816(Sa[j], qa[2 * g + 1], &kb[2]);
            }
        }

        const bool diag = (kt == qb);
#pragma unroll
        for (int j = 0; j < 16; j++) {
            const int c0 = kt * 128 + j * 8 + (lane & 3) * 2;
            float e0 = __expf(Sa[j][0]);
            float e1 = __expf(Sa[j][1]);
            float e2 = __expf(Sa[j][2]);
            float e3 = __expf(Sa[j][3]);
            if (diag) {
                if (c0     > r0) e0 = 0.0f;
                if (c0 + 1 > r0) e1 = 0.0f;
                if (c0     > r1) e2 = 0.0f;
                if (c0 + 1 > r1) e3 = 0.0f;
            }
            Sa[j][0] = e0; Sa[j][1] = e1; Sa[j][2] = e2; Sa[j][3] = e3;
            rs0 += e0 + e1; rs1 += e2 + e3;
        }

        uint32_t pa[8][4];
#pragma unroll
        for (int kc = 0; kc < 8; kc++) {
            pa[kc][0] = pack_h2(Sa[2*kc][0],   Sa[2*kc][1]);
            pa[kc][1] = pack_h2(Sa[2*kc][2],   Sa[2*kc][3]);
            pa[kc][2] = pack_h2(Sa[2*kc+1][0], Sa[2*kc+1][1]);
            pa[kc][3] = pack_h2(Sa[2*kc+1][2], Sa[2*kc+1][3]);
        }

#pragma unroll
        for (int g = 0; g < 4; g++) {
#pragma unroll
            for (int dt = 0; dt < 16; dt++) {
                uint32_t vb[4];
                ldsm4(vb, sVs + bbase + (uint32_t)(dt * 8 * FROWB + g * 64));
                mma16816(O[dt], pa[2 * g],     &vb[0]);
                mma16816(O[dt], pa[2 * g + 1], &vb[2]);
            }
        }
        __syncthreads();
    }

    rs0 += __shfl_xor_sync(0xffffffffu, rs0, 1);
    rs0 += __shfl_xor_sync(0xffffffffu, rs0, 2);
    rs1 += __shfl_xor_sync(0xffffffffu, rs1, 1);
    rs1 += __shfl_xor_sync(0xffffffffu, rs1, 2);
    const float inv0 = 1.0f / rs0;
    const float inv1 = 1.0f / rs1;

    if ((lane & 3) == 0) {
        invOut[(size_t)z * S_LEN + r0] = inv0;
        invOut[(size_t)z * S_LEN + r1] = inv1;
    }

    {
        __half* c0p = ctx + (size_t)(b * S_LEN + r0) * D_MODEL + h * HD;
        __half* c1p = ctx + (size_t)(b * S_LEN + r1) * D_MODEL + h * HD;
#pragma unroll
        for (int dt = 0; dt < 16; dt++) {
            const int c = dt * 8 + (lane & 3) * 2;
            *(__half2*)(c0p + c) = __floats2half2_rn(O[dt][0] * inv0, O[dt][1] * inv0);
            *(__half2*)(c1p + c) = __floats2half2_rn(O[dt][2] * inv1, O[dt][3] * inv1);
        }
    }
}

// ============================================================================
// Tail bodies: p2 (attn write) and oproj — merged for SM-level overlap.
// ============================================================================
__device__ void p2_body(
    const __half* __restrict__ Q, const __half* __restrict__ K,
    const float* __restrict__ invIn, float* __restrict__ attnF,
    int qb, int z)
{
    const int b  = z / NHEADS;
    const int h  = z % NHEADS;
    const int kv = h / NGRP;
    const int m0 = qb * 128;

    extern __shared__ __align__(16) char dsm[];
    const uint32_t sQ  = smem_u32(dsm);
    const uint32_t sK0 = sQ + FTILE;

    const int tid  = threadIdx.x;
    const int lane = tid & 31;
    const int w    = tid >> 5;

    const int frow = tid & 127;
    const int fhb  = (tid >> 7) * 64;

    {
        const __half* src = Q + (size_t)(b * S_LEN + m0 + frow) * D_MODEL + h * HD + fhb;
        const uint32_t dst = sQ + (uint32_t)(frow * FROWB + fhb * 2);
#pragma unroll
        for (int j = 0; j < 8; j++)
            sts16(dst + j * 16, *(const uint4*)(src + j * 8));
    }
    __syncthreads();

    uint32_t qa[8][4];
    {
        const uint32_t aoff = sQ + (uint32_t)((w * 16 + ((lane >> 3) & 1) * 8 + (lane & 7)) * FROWB
                                              + (lane >> 4) * 16);
#pragma unroll
        for (int kc = 0; kc < 8; kc++) ldsm4(qa[kc], aoff + kc * 32);
    }

    const int r0 = m0 + w * 16 + (lane >> 2);
    const int r1 = r0 + 8;
    const float inv0 = invIn[(size_t)z * S_LEN + r0];
    const float inv1 = invIn[(size_t)z * S_LEN + r1];

    const uint32_t bbase = (uint32_t)((lane & 7) * FROWB + (lane >> 3) * 16);
    const uint32_t fdst  = (uint32_t)(frow * FROWB + fhb * 2);

    auto issue_k = [&](int kt) {
        const uint32_t stK = sK0 + (uint32_t)(kt & 1) * FTILE;
        const __half* ksrc = K + (size_t)(b * S_LEN + kt * 128 + frow) * KVD + kv * HD + fhb;
#pragma unroll
        for (int j = 0; j < 8; j++)
            cpa16(stK + fdst + j * 16, ksrc + j * 8);
        CP_COMMIT();
    };

    float* arow0 = attnF + (size_t)z * S_LEN * S_LEN + (size_t)r0 * S_LEN;
    float* arow1 = attnF + (size_t)z * S_LEN * S_LEN + (size_t)r1 * S_LEN;

    issue_k(0);
    for (int kt = 0; kt <= qb; kt++) {
        if (kt < qb) { issue_k(kt + 1); CP_WAIT(1); }
        else         { CP_WAIT(0); }
        __syncthreads();

        const uint32_t sKs = sK0 + (uint32_t)(kt & 1) * FTILE;

        float Sa[16][4];
#pragma unroll
        for (int j = 0; j < 16; j++)
#pragma unroll
            for (int r = 0; r < 4; r++) Sa[j][r] = 0.0f;
#pragma unroll
        for (int g = 0; g < 4; g++) {
#pragma unroll
            for (int j = 0; j < 16; j++) {
                uint32_t kb[4];
                ldsm4(kb, sKs + bbase + (uint32_t)(j * 8 * FROWB + g * 64));
                mma16816(Sa[j], qa[2 * g],     &kb[0]);
                mma16816(Sa[j], qa[2 * g + 1], &kb[2]);
            }
        }

        const bool diag = (kt == qb);
#pragma unroll
        for (int j = 0; j < 16; j++) {
            const int c0 = kt * 128 + j * 8 + (lane & 3) * 2;
            float e0 = __expf(Sa[j][0]) * inv0;
            float e1 = __expf(Sa[j][1]) * inv0;
            float e2 = __expf(Sa[j][2]) * inv1;
            float e3 = __expf(Sa[j][3]) * inv1;
            if (diag) {
                if (c0     > r0) e0 = 0.0f;
                if (c0 + 1 > r0) e1 = 0.0f;
                if (c0     > r1) e2 = 0.0f;
                if (c0 + 1 > r1) e3 = 0.0f;
            }
            __stcs((float2*)(arow0 + c0), make_float2(e0, e1));
            __stcs((float2*)(arow1 + c0), make_float2(e2, e3));
        }
        __syncthreads();
    }

    {
        const int zstart = (qb + 1) * 128;
        const int row = m0 + (tid >> 1);
        float* p = attnF + (size_t)z * S_LEN * S_LEN + (size_t)row * S_LEN;
        for (int c = zstart + (tid & 1) * 4; c < S_LEN; c += 8)
            __stcs((float4*)(p + c), make_float4(0.0f, 0.0f, 0.0f, 0.0f));
    }
}

__device__ void oproj_body(
    const __half* __restrict__ X, const __half* __restrict__ W,
    const float* __restrict__ bias, float* __restrict__ C, int m0, int n0)
{
    extern __shared__ __align__(16) char dsm[];
    float acc[4][8][4];
    gemm_core(X, D_MODEL, W, D_MODEL, D_MODEL, m0, n0, smem_u32(dsm), acc);

    const int lane = threadIdx.x & 31;
    const int wid  = threadIdx.x >> 5;
    const int wm   = wid & 1;
    const int wn   = wid >> 1;
    const int rm   = m0 + wm * 64 + (lane >> 2);
#pragma unroll
    for (int tm = 0; tm < 4; tm++) {
        const int r = rm + tm * 16;
#pragma unroll
        for (int tn = 0; tn < 8; tn++) {
            const int c = n0 + wn * 64 + tn * 8 + (lane & 3) * 2;
            const float b0 = bias[c];
            const float b1 = bias[c + 1];
            *(float2*)(C + (size_t)r       * D_MODEL + c) =
                make_float2(acc[tm][tn][0] + b0, acc[tm][tn][1] + b1);
            *(float2*)(C + (size_t)(r + 8) * D_MODEL + c) =
                make_float2(acc[tm][tn][2] + b0, acc[tm][tn][3] + b1);
        }
    }
}

// Merged tail: with attn output, 768 CTAs (every 3rd = oproj, rest = p2).
// Without: 256 CTAs, all oproj.
__global__ __launch_bounds__(256, 1) void tail_kernel(
    const __half* __restrict__ Q, const __half* __restrict__ K,
    const float* __restrict__ invIn, float* __restrict__ attnF,
    const __half* __restrict__ ctx, const __half* __restrict__ Wo,
    const float* __restrict__ bo, float* __restrict__ out, int writeP)
{
    const int bid = blockIdx.x;
    if (writeP) {
        if (bid % 3 == 2) {
            const int oidx = bid / 3;                    // 0..255
            oproj_body(ctx, Wo, bo, out, (oidx >> 3) * 128, (oidx & 7) * 256);
        } else {
            const int pidx = (bid / 3) * 2 + (bid % 3);  // 0..511
            const int qb = 15 - (pidx & 15);             // long CTAs first
            const int z  = pidx >> 4;
            p2_body(Q, K, invIn, attnF, qb, z);
        }
    } else {
        oproj_body(ctx, Wo, bo, out, (bid >> 3) * 128, (bid & 7) * 256);
    }
}

// ============================================================================
// Launch
// ============================================================================
extern "C" void kernel_launch(void* const* d_in, const int* in_sizes, int n_in,
                              void* d_out, int out_size)
{
    const float* query = (const float*)d_in[0];
    const float* Wq = (const float*)d_in[2];
    const float* bq = (const float*)d_in[3];
    const float* Wk = (const float*)d_in[4];
    const float* bk = (const float*)d_in[5];
    const float* Wv = (const float*)d_in[6];
    const float* bv = (const float*)d_in[7];
    const float* Wo = (const float*)d_in[8];
    const float* bo = (const float*)d_in[9];
    float* out = (float*)d_out;

    __half *pXh, *pWqkv, *pWoh, *pQ, *pK, *pV, *pVt, *pCtx;
    float *pInv;
    cudaGetSymbolAddress((void**)&pXh,   g_Xh);
    cudaGetSymbolAddress((void**)&pWqkv, g_Wqkv);
    cudaGetSymbolAddress((void**)&pWoh,  g_Woh);
    cudaGetSymbolAddress((void**)&pQ,    g_Qh);
    cudaGetSymbolAddress((void**)&pK,    g_Kh);
    cudaGetSymbolAddress((void**)&pV,    g_Vh);
    cudaGetSymbolAddress((void**)&pVt,   g_VtH);
    cudaGetSymbolAddress((void**)&pCtx,  g_ctxH);
    cudaGetSymbolAddress((void**)&pInv,  g_inv);

    const long long OUT_ELEMS  = (long long)MROWS * D_MODEL;
    const long long ATTN_ELEMS = (long long)BATCH * NHEADS * S_LEN * S_LEN;
    float* attnF = out;
    int writeP = 0;
    if ((long long)out_size >= OUT_ELEMS + ATTN_ELEMS) {
        attnF = out + OUT_ELEMS;
        writeP = 1;
    }

    const int SMEM_G  = 3 * STAGE;   // 92160
    const int SMEM_F1 = 5 * FTILE;   // 174080
    const int SMEM_T  = 3 * FTILE;   // 104448 (max of p2 104448 / oproj 92160)
    cudaFuncSetAttribute(qkv_kernel,  cudaFuncAttributeMaxDynamicSharedMemorySize, SMEM_G);
    cudaFuncSetAttribute(flash_fwd,   cudaFuncAttributeMaxDynamicSharedMemorySize, SMEM_F1);
    cudaFuncSetAttribute(tail_kernel, cudaFuncAttributeMaxDynamicSharedMemorySize, SMEM_T);

    const float qscale = 0.08838834764831845f;  // 1/sqrt(128)

    // 0: fused conversion (one launch)
    cvt_all_kernel<<<(N4_ALL + 255) / 256, 256>>>(
        query, Wq, Wk, Wv, Wo, pXh, pWqkv, pWoh);

    // 1: fused QKV projection
    qkv_kernel<<<dim3(NQKV/256, MROWS/128), 256, SMEM_G>>>(
        pXh, pWqkv, bq, bk, bv, pQ, pK, pV, qscale);

    // 2: RoPE
    {
        int total_threads = 2 * MROWS * KVD / 2;
        rope_kernel<<<(total_threads + 255) / 256, 256>>>(pK, pV, pVt);
    }

    // 3: flash forward (ctx + inv)
    flash_fwd<<<dim3(S_LEN/128, BATCH*NHEADS), 256, SMEM_F1>>>(
        pQ, pK, pVt, pCtx, pInv);

    // 4: merged tail — attn write + O projection co-resident
    {
        const int nblk = writeP ? 768 : 256;
        tail_kernel<<<nblk, 256, SMEM_T>>>(
            pQ, pK, pInv, attnF, pCtx, pWoh, bo, out, writeP);
    }
}

// round 16
// speedup vs baseline: 1.0177x; 1.0177x over previous
#include <cuda_runtime.h>
#include <cuda_fp16.h>
#include <math.h>
#include <stdint.h>

#define D_MODEL 2048
#define S_LEN   2048
#define BATCH   2
#define NHEADS  16
#define NKV     4
#define NGRP    4
#define HD      128
#define KVD     (NKV*HD)        /* 512  */
#define MROWS   (BATCH*S_LEN)   /* 4096 */
#define NQKV    (D_MODEL + 2*KVD)   /* 3072 */

// -------- scratch (device globals; no allocation allowed) --------
__device__ __half g_Xh  [(size_t)MROWS * D_MODEL];
__device__ __half g_Wqkv[(size_t)NQKV * D_MODEL];
__device__ __half g_Woh [(size_t)D_MODEL * D_MODEL];
__device__ __half g_Qh  [(size_t)MROWS * D_MODEL];
__device__ __half g_Kh  [(size_t)MROWS * KVD];
__device__ __half g_Vh  [(size_t)MROWS * KVD];
__device__ __half g_VtH [(size_t)BATCH * NKV * HD * S_LEN];
__device__ __half g_ctxH[(size_t)MROWS * D_MODEL];
__device__ float  g_inv [(size_t)BATCH * NHEADS * S_LEN];
__device__ __half g_P   [(size_t)BATCH * NHEADS * S_LEN * S_LEN];   // 256 MB

// ---------------- helpers ----------------
__device__ __forceinline__ uint32_t smem_u32(const void* p) {
    uint32_t a;
    asm("{ .reg .u64 t; cvta.to.shared.u64 t, %1; cvt.u32.u64 %0, t; }"
        : "=r"(a) : "l"(p));
    return a;
}
__device__ __forceinline__ void ldsm4(uint32_t* r, uint32_t addr) {
    asm volatile("ldmatrix.sync.aligned.m8n8.x4.shared.b16 {%0,%1,%2,%3}, [%4];"
        : "=r"(r[0]), "=r"(r[1]), "=r"(r[2]), "=r"(r[3]) : "r"(addr));
}
__device__ __forceinline__ void mma16816(float* d, const uint32_t* a, const uint32_t* b) {
    asm volatile(
        "mma.sync.aligned.m16n8k16.row.col.f32.f16.f16.f32 "
        "{%0,%1,%2,%3}, {%4,%5,%6,%7}, {%8,%9}, {%0,%1,%2,%3};"
        : "+f"(d[0]), "+f"(d[1]), "+f"(d[2]), "+f"(d[3])
        : "r"(a[0]), "r"(a[1]), "r"(a[2]), "r"(a[3]), "r"(b[0]), "r"(b[1]));
}
__device__ __forceinline__ void sts16(uint32_t addr, uint4 u) {
    asm volatile("st.shared.v4.b32 [%0], {%1,%2,%3,%4};"
        :: "r"(addr), "r"(u.x), "r"(u.y), "r"(u.z), "r"(u.w) : "memory");
}
__device__ __forceinline__ void cpa16(uint32_t dst, const void* src) {
    asm volatile("cp.async.cg.shared.global [%0], [%1], 16;"
        :: "r"(dst), "l"(src) : "memory");
}
#define CP_COMMIT() asm volatile("cp.async.commit_group;" ::: "memory")
#define CP_WAIT(n)  asm volatile("cp.async.wait_group %0;" :: "n"(n) : "memory")
__device__ __forceinline__ uint32_t pack_h2(float a, float b) {
    __half2 h = __floats2half2_rn(a, b);
    return *(uint32_t*)&h;
}
__device__ __forceinline__ void st_h2_cs(__half* p, uint32_t v) {
    __stcs((__half2*)p, *(__half2*)&v);
}

// ============================================================================
// Fused fp32 -> fp16 conversion (one launch)
// ============================================================================
#define N4_X  (MROWS * D_MODEL / 4)
#define N4_WQ (D_MODEL * D_MODEL / 4)
#define N4_WK (KVD * D_MODEL / 4)
#define N4_ALL (N4_X + N4_WQ + 2*N4_WK + N4_WQ)

__global__ void cvt_all_kernel(
    const float* __restrict__ X,  const float* __restrict__ Wq,
    const float* __restrict__ Wk, const float* __restrict__ Wv,
    const float* __restrict__ Wo,
    __half* __restrict__ Xh, __half* __restrict__ Wqkv, __half* __restrict__ Woh)
{
    int i = blockIdx.x * blockDim.x + threadIdx.x;
    if (i >= N4_ALL) return;
    const float* src; __half* dst; int off;
    if (i < N4_X) {
        src = X; dst = Xh; off = 0;
    } else if (i < N4_X + N4_WQ) {
        src = Wq; dst = Wqkv; off = N4_X;
    } else if (i < N4_X + N4_WQ + N4_WK) {
        src = Wk; dst = Wqkv + (size_t)D_MODEL * D_MODEL; off = N4_X + N4_WQ;
    } else if (i < N4_X + N4_WQ + 2 * N4_WK) {
        src = Wv; dst = Wqkv + (size_t)(D_MODEL + KVD) * D_MODEL; off = N4_X + N4_WQ + N4_WK;
    } else {
        src = Wo; dst = Woh; off = N4_X + N4_WQ + 2 * N4_WK;
    }
    const int j = i - off;
    float4 v = ((const float4*)src)[j];
    __half2 h0 = __floats2half2_rn(v.x, v.y);
    __half2 h1 = __floats2half2_rn(v.z, v.w);
    uint2 u; u.x = *(uint32_t*)&h0; u.y = *(uint32_t*)&h1;
    ((uint2*)dst)[j] = u;
}

// ============================================================================
// All-half GEMM core, 3-stage cp.async pipeline (proven).
// ============================================================================
#define ROWB   80
#define AB_SZ  (128 * ROWB)
#define BB_SZ  (256 * ROWB)
#define STAGE  (AB_SZ + BB_SZ)

__device__ __forceinline__ void gemm_core(
    const __half* __restrict__ A, int lda,
    const __half* __restrict__ B, int ldb,
    int Kd, int m0, int n0, uint32_t sb, float (&acc)[4][8][4])
{
    const int tid  = threadIdx.x;
    const int lane = tid & 31;
    const int wid  = tid >> 5;
    const int wm   = wid & 1;
    const int wn   = wid >> 1;

#pragma unroll
    for (int i = 0; i < 4; i++)
#pragma unroll
        for (int j = 0; j < 8; j++)
#pragma unroll
            for (int r = 0; r < 4; r++) acc[i][j][r] = 0.0f;

    const uint32_t aoff = (uint32_t)((wm * 64 + ((lane >> 3) & 1) * 8 + (lane & 7)) * ROWB
                                     + (lane >> 4) * 16);
    const uint32_t boff = (uint32_t)((wn * 64 + (lane & 7)) * ROWB + (lane >> 3) * 16);

    const int nc = Kd >> 5;

    auto issue = [&](int c) {
        const uint32_t st = sb + (uint32_t)(c % 3) * STAGE;
        const int kc = c * 32;
#pragma unroll
        for (int i = 0; i < 2; i++) {
            const int idx = tid + i * 256;
            const int row = idx >> 2, k8 = idx & 3;
            cpa16(st + (uint32_t)(row * ROWB + k8 * 16),
                  A + (size_t)(m0 + row) * lda + kc + k8 * 8);
        }
#pragma unroll
        for (int i = 0; i < 4; i++) {
            const int idx = tid + i * 256;
            const int row = idx >> 2, k8 = idx & 3;
            cpa16(st + AB_SZ + (uint32_t)(row * ROWB + k8 * 16),
                  B + (size_t)(n0 + row) * ldb + kc + k8 * 8);
        }
        CP_COMMIT();
    };

    issue(0);
    if (nc > 1) issue(1);

    for (int c = 0; c < nc; c++) {
        if (c + 2 < nc)      { issue(c + 2); CP_WAIT(2); }
        else if (c + 1 < nc) { CP_WAIT(1); }
        else                 { CP_WAIT(0); }
        __syncthreads();

        const uint32_t sA = sb + (uint32_t)(c % 3) * STAGE;
        const uint32_t sB = sA + AB_SZ;
        uint32_t bfr[8][4];
#pragma unroll
        for (int tn = 0; tn < 8; tn++)
            ldsm4(bfr[tn], sB + boff + tn * 8 * ROWB);
#pragma unroll
        for (int tm = 0; tm < 4; tm++) {
            uint32_t a0[4], a1[4];
            ldsm4(a0, sA + aoff + tm * 16 * ROWB);
            ldsm4(a1, sA + aoff + tm * 16 * ROWB + 32);
#pragma unroll
            for (int tn = 0; tn < 8; tn++) {
                mma16816(acc[tm][tn], a0, &bfr[tn][0]);
                mma16816(acc[tm][tn], a1, &bfr[tn][2]);
            }
        }
        __syncthreads();
    }
}

// ============================================================================
// QKV projection
// ============================================================================
__global__ __launch_bounds__(256, 1) void qkv_kernel(
    const __half* __restrict__ X, const __half* __restrict__ Wqkv,
    const float* __restrict__ bq, const float* __restrict__ bk, const float* __restrict__ bv,
    __half* __restrict__ Qo, __half* __restrict__ Ko, __half* __restrict__ Vo,
    float qscale)
{
    extern __shared__ __align__(16) char dsm[];
    const int m0 = blockIdx.y * 128;
    const int n0 = blockIdx.x * 256;

    float acc[4][8][4];
    gemm_core(X, D_MODEL, Wqkv, D_MODEL, D_MODEL, m0, n0, smem_u32(dsm), acc);

    __half* C; const float* bias; int ldc, nbase; float scale;
    if (n0 < D_MODEL)            { C = Qo; bias = bq; ldc = D_MODEL; nbase = 0;              scale = qscale; }
    else if (n0 < D_MODEL + KVD) { C = Ko; bias = bk; ldc = KVD;     nbase = D_MODEL;        scale = 1.0f; }
    else                         { C = Vo; bias = bv; ldc = KVD;     nbase = D_MODEL + KVD;  scale = 1.0f; }

    const int lane = threadIdx.x & 31;
    const int wid  = threadIdx.x >> 5;
    const int wm   = wid & 1;
    const int wn   = wid >> 1;
    const int rm   = m0 + wm * 64 + (lane >> 2);
#pragma unroll
    for (int tm = 0; tm < 4; tm++) {
        const int r = rm + tm * 16;
#pragma unroll
        for (int tn = 0; tn < 8; tn++) {
            const int c = n0 - nbase + wn * 64 + tn * 8 + (lane & 3) * 2;
            const float b0 = bias[c];
            const float b1 = bias[c + 1];
            *(__half2*)(C + (size_t)r       * ldc + c) =
                __floats2half2_rn((acc[tm][tn][0] + b0) * scale, (acc[tm][tn][1] + b1) * scale);
            *(__half2*)(C + (size_t)(r + 8) * ldc + c) =
                __floats2half2_rn((acc[tm][tn][2] + b0) * scale, (acc[tm][tn][3] + b1) * scale);
        }
    }
}

// ============================================================================
// O projection
// ============================================================================
__global__ __launch_bounds__(256, 1) void oproj_kernel(
    const __half* __restrict__ X, const __half* __restrict__ W,
    const float* __restrict__ bias, float* __restrict__ C)
{
    extern __shared__ __align__(16) char dsm[];
    const int m0 = blockIdx.y * 128;
    const int n0 = blockIdx.x * 256;

    float acc[4][8][4];
    gemm_core(X, D_MODEL, W, D_MODEL, D_MODEL, m0, n0, smem_u32(dsm), acc);

    const int lane = threadIdx.x & 31;
    const int wid  = threadIdx.x >> 5;
    const int wm   = wid & 1;
    const int wn   = wid >> 1;
    const int rm   = m0 + wm * 64 + (lane >> 2);
#pragma unroll
    for (int tm = 0; tm < 4; tm++) {
        const int r = rm + tm * 16;
#pragma unroll
        for (int tn = 0; tn < 8; tn++) {
            const int c = n0 + wn * 64 + tn * 8 + (lane & 3) * 2;
            const float b0 = bias[c];
            const float b1 = bias[c + 1];
            *(float2*)(C + (size_t)r       * D_MODEL + c) =
                make_float2(acc[tm][tn][0] + b0, acc[tm][tn][1] + b1);
            *(float2*)(C + (size_t)(r + 8) * D_MODEL + c) =
                make_float2(acc[tm][tn][2] + b0, acc[tm][tn][3] + b1);
        }
    }
}

// ============================================================================
// RoPE
// ============================================================================
__global__ void rope_kernel(__half* __restrict__ K, const __half* __restrict__ V,
                            __half* __restrict__ Vt)
{
    const int total = MROWS * KVD / 2;
    int idx = blockIdx.x * blockDim.x + threadIdx.x;
    if (idx >= 2 * total) return;
    const bool isK = (idx < total);
    int i = isK ? idx : idx - total;

    const int pair = i & 63;
    const int rest = i >> 6;
    const int kvi  = rest & (NKV - 1);
    const int row  = rest / NKV;
    const int s    = row & (S_LEN - 1);
    const int b    = row >> 11;

    const float inv_freq = powf(10000.0f, -(float)(2 * pair) / (float)HD);
    const float ang = (float)s * inv_freq;
    const float c = cosf(ang), sn = sinf(ang);

    const size_t base = (size_t)row * KVD + kvi * HD;
    if (isK) {
        float x1 = __half2float(K[base + pair]);
        float x2 = __half2float(K[base + pair + 64]);
        K[base + pair]      = __float2half_rn(x1 * c - x2 * sn);
        K[base + pair + 64] = __float2half_rn(x2 * c + x1 * sn);
    } else {
        float x1 = __half2float(V[base + pair]);
        float x2 = __half2float(V[base + pair + 64]);
        __half* vt = Vt + (size_t)(b * NKV + kvi) * HD * S_LEN;
        vt[(size_t)pair * S_LEN + s]        = __float2half_rn(x1 * c - x2 * sn);
        vt[(size_t)(pair + 64) * S_LEN + s] = __float2half_rn(x2 * c + x1 * sn);
    }
}

// ============================================================================
// Flash forward: scores + exp + AV -> ctx, per-row inv saved,
// and (writeP) unnormalized P stored as half (reusing the pa fragments).
// ============================================================================
#define FROWB 272
#define FTILE (128 * FROWB)

__global__ __launch_bounds__(256) void flash_fwd(
    const __half* __restrict__ Q, const __half* __restrict__ K,
    const __half* __restrict__ Vt, __half* __restrict__ ctx,
    float* __restrict__ invOut, __half* __restrict__ P, int writeP)
{
    const int qb = gridDim.x - 1 - blockIdx.x;
    const int z  = blockIdx.y;
    const int b  = z / NHEADS;
    const int h  = z % NHEADS;
    const int kv = h / NGRP;
    const int m0 = qb * 128;

    extern __shared__ __align__(16) char dsm[];
    const uint32_t sQ  = smem_u32(dsm);
    const uint32_t sK0 = sQ + FTILE;
    const uint32_t sV0 = sQ + 3 * FTILE;

    const int tid  = threadIdx.x;
    const int lane = tid & 31;
    const int w    = tid >> 5;

    const int frow = tid & 127;
    const int fhb  = (tid >> 7) * 64;

    {
        const __half* src = Q + (size_t)(b * S_LEN + m0 + frow) * D_MODEL + h * HD + fhb;
        const uint32_t dst = sQ + (uint32_t)(frow * FROWB + fhb * 2);
#pragma unroll
        for (int j = 0; j < 8; j++)
            sts16(dst + j * 16, *(const uint4*)(src + j * 8));
    }
    __syncthreads();

    uint32_t qa[8][4];
    {
        const uint32_t aoff = sQ + (uint32_t)((w * 16 + ((lane >> 3) & 1) * 8 + (lane & 7)) * FROWB
                                              + (lane >> 4) * 16);
#pragma unroll
        for (int kc = 0; kc < 8; kc++) ldsm4(qa[kc], aoff + kc * 32);
    }

    const int r0 = m0 + w * 16 + (lane >> 2);
    const int r1 = r0 + 8;
    __half* Pr0 = P + (size_t)z * S_LEN * S_LEN + (size_t)r0 * S_LEN;
    __half* Pr1 = P + (size_t)z * S_LEN * S_LEN + (size_t)r1 * S_LEN;

    float O[16][4];
#pragma unroll
    for (int dt = 0; dt < 16; dt++)
#pragma unroll
        for (int r = 0; r < 4; r++) O[dt][r] = 0.0f;
    float rs0 = 0.0f, rs1 = 0.0f;

    const uint32_t bbase = (uint32_t)((lane & 7) * FROWB + (lane >> 3) * 16);
    const uint32_t fdst  = (uint32_t)(frow * FROWB + fhb * 2);

    auto issue_kv = [&](int kt) {
        const uint32_t stK = sK0 + (uint32_t)(kt & 1) * FTILE;
        const uint32_t stV = sV0 + (uint32_t)(kt & 1) * FTILE;
        const __half* ksrc = K + (size_t)(b * S_LEN + kt * 128 + frow) * KVD + kv * HD + fhb;
        const __half* vsrc = Vt + (size_t)((b * NKV + kv) * HD + frow) * S_LEN + kt * 128 + fhb;
#pragma unroll
        for (int j = 0; j < 8; j++) {
            cpa16(stK + fdst + j * 16, ksrc + j * 8);
            cpa16(stV + fdst + j * 16, vsrc + j * 8);
        }
        CP_COMMIT();
    };

    issue_kv(0);
    for (int kt = 0; kt <= qb; kt++) {
        if (kt < qb) { issue_kv(kt + 1); CP_WAIT(1); }
        else         { CP_WAIT(0); }
        __syncthreads();

        const uint32_t sKs = sK0 + (uint32_t)(kt & 1) * FTILE;
        const uint32_t sVs = sV0 + (uint32_t)(kt & 1) * FTILE;

        float Sa[16][4];
#pragma unroll
        for (int j = 0; j < 16; j++)
#pragma unroll
            for (int r = 0; r < 4; r++) Sa[j][r] = 0.0f;
#pragma unroll
        for (int g = 0; g < 4; g++) {
#pragma unroll
            for (int j = 0; j < 16; j++) {
                uint32_t kb[4];
                ldsm4(kb, sKs + bbase + (uint32_t)(j * 8 * FROWB + g * 64));
                mma16816(Sa[j], qa[2 * g],     &kb[0]);
                mma16816(Sa[j], qa[2 * g + 1], &kb[2]);
            }
        }

        const bool diag = (kt == qb);
#pragma unroll
        for (int j = 0; j < 16; j++) {
            const int c0 = kt * 128 + j * 8 + (lane & 3) * 2;
            float e0 = __expf(Sa[j][0]);
            float e1 = __expf(Sa[j][1]);
            float e2 = __expf(Sa[j][2]);
            float e3 = __expf(Sa[j][3]);
            if (diag) {
                if (c0     > r0) e0 = 0.0f;
                if (c0 + 1 > r0) e1 = 0.0f;
                if (c0     > r1) e2 = 0.0f;
                if (c0 + 1 > r1) e3 = 0.0f;
            }
            Sa[j][0] = e0; Sa[j][1] = e1; Sa[j][2] = e2; Sa[j][3] = e3;
            rs0 += e0 + e1; rs1 += e2 + e3;
        }

        uint32_t pa[8][4];
#pragma unroll
        for (int kc = 0; kc < 8; kc++) {
            pa[kc][0] = pack_h2(Sa[2*kc][0],   Sa[2*kc][1]);
            pa[kc][1] = pack_h2(Sa[2*kc][2],   Sa[2*kc][3]);
            pa[kc][2] = pack_h2(Sa[2*kc+1][0], Sa[2*kc+1][1]);
            pa[kc][3] = pack_h2(Sa[2*kc+1][2], Sa[2*kc+1][3]);
        }

        // store unnormalized P (reusing pa fragments; no extra converts)
        if (writeP) {
            const int cb = kt * 128 + (lane & 3) * 2;
#pragma unroll
            for (int kc = 0; kc < 8; kc++) {
                st_h2_cs(Pr0 + cb + 2*kc*8,       pa[kc][0]);
                st_h2_cs(Pr0 + cb + (2*kc+1)*8,   pa[kc][2]);
                st_h2_cs(Pr1 + cb + 2*kc*8,       pa[kc][1]);
                st_h2_cs(Pr1 + cb + (2*kc+1)*8,   pa[kc][3]);
            }
        }

#pragma unroll
        for (int g = 0; g < 4; g++) {
#pragma unroll
            for (int dt = 0; dt < 16; dt++) {
                uint32_t vb[4];
                ldsm4(vb, sVs + bbase + (uint32_t)(dt * 8 * FROWB + g * 64));
                mma16816(O[dt], pa[2 * g],     &vb[0]);
                mma16816(O[dt], pa[2 * g + 1], &vb[2]);
            }
        }
        __syncthreads();
    }

    rs0 += __shfl_xor_sync(0xffffffffu, rs0, 1);
    rs0 += __shfl_xor_sync(0xffffffffu, rs0, 2);
    rs1 += __shfl_xor_sync(0xffffffffu, rs1, 1);
    rs1 += __shfl_xor_sync(0xffffffffu, rs1, 2);
    const float inv0 = 1.0f / rs0;
    const float inv1 = 1.0f / rs1;

    if ((lane & 3) == 0) {
        invOut[(size_t)z * S_LEN + r0] = inv0;
        invOut[(size_t)z * S_LEN + r1] = inv1;
    }

    {
        __half* c0p = ctx + (size_t)(b * S_LEN + r0) * D_MODEL + h * HD;
        __half* c1p = ctx + (size_t)(b * S_LEN + r1) * D_MODEL + h * HD;
#pragma unroll
        for (int dt = 0; dt < 16; dt++) {
            const int c = dt * 8 + (lane & 3) * 2;
            *(__half2*)(c0p + c) = __floats2half2_rn(O[dt][0] * inv0, O[dt][1] * inv0);
            *(__half2*)(c1p + c) = __floats2half2_rn(O[dt][2] * inv1, O[dt][3] * inv1);
        }
    }
}

// ============================================================================
// p2_scale: attn = P_half * inv (fp32), zero-fill beyond causal bound.
// Pure DRAM streaming; one block per (z, q) row.
// ============================================================================
__global__ __launch_bounds__(256) void p2_scale(
    const __half* __restrict__ P, const float* __restrict__ invIn,
    float* __restrict__ attnF)
{
    const int gr = blockIdx.x;          // 0..65535
    const int z  = gr >> 11;
    const int q  = gr & (S_LEN - 1);
    const float iv = invIn[(size_t)z * S_LEN + q];
    const int len = (q | 127) + 1;      // stored region (masked zeros included)

    const __half* src = P + (size_t)z * S_LEN * S_LEN + (size_t)q * S_LEN;
    float* dst = attnF + (size_t)z * S_LEN * S_LEN + (size_t)q * S_LEN;

    const int c0 = threadIdx.x * 8;     // 8 cols per thread, 2048 cols total
    if (c0 < len) {
        uint4 pv = __ldcs((const uint4*)(src + c0));
        const __half2* h = (const __half2*)&pv;
        float4 o0, o1;
        float2 f0 = __half22float2(h[0]);
        float2 f1 = __half22float2(h[1]);
        float2 f2 = __half22float2(h[2]);
        float2 f3 = __half22float2(h[3]);
        o0.x = f0.x * iv; o0.y = f0.y * iv; o0.z = f1.x * iv; o0.w = f1.y * iv;
        o1.x = f2.x * iv; o1.y = f2.y * iv; o1.z = f3.x * iv; o1.w = f3.y * iv;
        __stcs((float4*)(dst + c0), o0);
        __stcs((float4*)(dst + c0 + 4), o1);
    } else {
        const float4 zz = make_float4(0.0f, 0.0f, 0.0f, 0.0f);
        __stcs((float4*)(dst + c0), zz);
        __stcs((float4*)(dst + c0 + 4), zz);
    }
}

// ============================================================================
// Launch — fork: p2_scale (DRAM) overlaps oproj (tensor)
// ============================================================================
extern "C" void kernel_launch(void* const* d_in, const int* in_sizes, int n_in,
                              void* d_out, int out_size)
{
    const float* query = (const float*)d_in[0];
    const float* Wq = (const float*)d_in[2];
    const float* bq = (const float*)d_in[3];
    const float* Wk = (const float*)d_in[4];
    const float* bk = (const float*)d_in[5];
    const float* Wv = (const float*)d_in[6];
    const float* bv = (const float*)d_in[7];
    const float* Wo = (const float*)d_in[8];
    const float* bo = (const float*)d_in[9];
    float* out = (float*)d_out;

    __half *pXh, *pWqkv, *pWoh, *pQ, *pK, *pV, *pVt, *pCtx, *pP;
    float *pInv;
    cudaGetSymbolAddress((void**)&pXh,   g_Xh);
    cudaGetSymbolAddress((void**)&pWqkv, g_Wqkv);
    cudaGetSymbolAddress((void**)&pWoh,  g_Woh);
    cudaGetSymbolAddress((void**)&pQ,    g_Qh);
    cudaGetSymbolAddress((void**)&pK,    g_Kh);
    cudaGetSymbolAddress((void**)&pV,    g_Vh);
    cudaGetSymbolAddress((void**)&pVt,   g_VtH);
    cudaGetSymbolAddress((void**)&pCtx,  g_ctxH);
    cudaGetSymbolAddress((void**)&pP,    g_P);
    cudaGetSymbolAddress((void**)&pInv,  g_inv);

    const long long OUT_ELEMS  = (long long)MROWS * D_MODEL;
    const long long ATTN_ELEMS = (long long)BATCH * NHEADS * S_LEN * S_LEN;
    float* attnF = out;
    int writeP = 0;
    if ((long long)out_size >= OUT_ELEMS + ATTN_ELEMS) {
        attnF = out + OUT_ELEMS;
        writeP = 1;
    }

    const int SMEM_G  = 3 * STAGE;   // 92160
    const int SMEM_F1 = 5 * FTILE;   // 174080
    cudaFuncSetAttribute(qkv_kernel,   cudaFuncAttributeMaxDynamicSharedMemorySize, SMEM_G);
    cudaFuncSetAttribute(oproj_kernel, cudaFuncAttributeMaxDynamicSharedMemorySize, SMEM_G);
    cudaFuncSetAttribute(flash_fwd,    cudaFuncAttributeMaxDynamicSharedMemorySize, SMEM_F1);

    const float qscale = 0.08838834764831845f;  // 1/sqrt(128)

    // 0: fused conversion
    cvt_all_kernel<<<(N4_ALL + 255) / 256, 256>>>(
        query, Wq, Wk, Wv, Wo, pXh, pWqkv, pWoh);

    // 1: fused QKV projection
    qkv_kernel<<<dim3(NQKV/256, MROWS/128), 256, SMEM_G>>>(
        pXh, pWqkv, bq, bk, bv, pQ, pK, pV, qscale);

    // 2: RoPE
    {
        int total_threads = 2 * MROWS * KVD / 2;
        rope_kernel<<<(total_threads + 255) / 256, 256>>>(pK, pV, pVt);
    }

    // 3: flash forward (ctx + inv + raw P)
    flash_fwd<<<dim3(S_LEN/128, BATCH*NHEADS), 256, SMEM_F1>>>(
        pQ, pK, pVt, pCtx, pInv, pP, writeP);

    // 4+5: fork — p2_scale on s2 overlaps oproj on main stream
    cudaStream_t s2 = 0;
    cudaEvent_t eFork = 0, eJoin = 0;
    bool forked = false;
    if (writeP) {
        if (cudaStreamCreateWithFlags(&s2, cudaStreamNonBlocking) == cudaSuccess) {
            cudaEventCreateWithFlags(&eFork, cudaEventDisableTiming);
            cudaEventCreateWithFlags(&eJoin, cudaEventDisableTiming);
            cudaEventRecord(eFork, 0);
            cudaStreamWaitEvent(s2, eFork, 0);
            p2_scale<<<BATCH * NHEADS * S_LEN, 256, 0, s2>>>(pP, pInv, attnF);
            cudaEventRecord(eJoin, s2);
            forked = true;
        } else {
            p2_scale<<<BATCH * NHEADS * S_LEN, 256>>>(pP, pInv, attnF);
        }
    }

    oproj_kernel<<<dim3(D_MODEL/256, MROWS/128), 256, SMEM_G>>>(pCtx, pWoh, bo, out);

    if (forked) {
        cudaStreamWaitEvent(0, eJoin, 0);
        cudaEventDestroy(eFork);
        cudaEventDestroy(eJoin);
        cudaStreamDestroy(s2);
    }
}